// round 2
// baseline (speedup 1.0000x reference)
#include <cuda_runtime.h>
#include <stdint.h>

// TDGSPooling2d: gumbel-softmax hard pooling over 2x2 patches.
// out[b,c,ho,wo] = x_patch[argmax_k(x_patch[k]/temp[c,ho,wo] + g_k)]
//
// Noise: JAX *partitionable* threefry (default since JAX 0.4.36):
//   bits[i] = o0 ^ o1, (o0,o1) = threefry2x32(key=(0,42), counter=(0, i))
// (64-bit per-element counter; hi word is 0 since size < 2^32)
// u = bitcast(bits>>9 | 0x3f800000) - 1; u = max(1e-20, u); g = -log(-log(u))

// ---------- threefry2x32, key = (0, 42), counter (0, c1), return o0^o1 ----
// ks0 = 0, ks1 = 42, ks2 = 0x1BD11BDA ^ 0 ^ 42 = 0x1BD11BF0
__device__ __forceinline__ uint32_t tf_xor_0_42(uint32_t c1) {
    const uint32_t ks1 = 42u;
    const uint32_t ks2 = 0x1BD11BF0u;
    uint32_t x0 = 0u;            // c0 (=0) + ks0 (=0)
    uint32_t x1 = c1 + ks1;
#define TFR(r) { x0 += x1; x1 = __funnelshift_l(x1, x1, r); x1 ^= x0; }
    TFR(13) TFR(15) TFR(26) TFR(6)
    x0 += ks1; x1 += ks2 + 1u;
    TFR(17) TFR(29) TFR(16) TFR(24)
    x0 += ks2; x1 += 2u;                 // ks0 + 2
    TFR(13) TFR(15) TFR(26) TFR(6)
    /* x0 += ks0 (=0) */ x1 += ks1 + 3u;
    TFR(17) TFR(29) TFR(16) TFR(24)
    x0 += ks1; x1 += ks2 + 4u;
    TFR(13) TFR(15) TFR(26) TFR(6)
    x0 += ks2; x1 += 5u;                 // ks0 + 5
#undef TFR
    return x0 ^ x1;
}

// ---------- accurate logf (Cephes/Eigen plog polynomial, ~1 ulp) ----------
// Matches XLA-CPU's Eigen plog bit-for-bit on the fast path.
__device__ __forceinline__ float flog_acc(float a) {
    int bits = __float_as_int(a);
    int e = (bits >> 23) - 126;                                  // frexp exp
    float m = __int_as_float((bits & 0x007fffff) | 0x3f000000);  // [0.5, 1)
    if (m < 0.707106781186547524f) { e -= 1; m = m + m; }        // [sqrt.5, sqrt2)
    float x = m - 1.0f;
    float z = x * x;
    float y = 7.0376836292e-2f;
    y = fmaf(y, x, -1.1514610310e-1f);
    y = fmaf(y, x,  1.1676998740e-1f);
    y = fmaf(y, x, -1.2420140846e-1f);
    y = fmaf(y, x,  1.4249322787e-1f);
    y = fmaf(y, x, -1.6668057665e-1f);
    y = fmaf(y, x,  2.0000714765e-1f);
    y = fmaf(y, x, -2.4999993993e-1f);
    y = fmaf(y, x,  3.3333331174e-1f);
    y = y * x;
    y = y * z;
    float fe = (float)e;
    y = fmaf(fe, -2.12194440e-4f, y);
    y = fmaf(-0.5f, z, y);
    float r = x + y;
    r = fmaf(fe, 0.693359375f, r);
    return r;
}

// bits -> uniform (JAX recipe) -> gumbel
__device__ __forceinline__ float gumbel_from_bits(uint32_t bits) {
    float u = __uint_as_float((bits >> 9) | 0x3f800000u) - 1.0f;
    u = fmaxf(u, 1e-20f);        // floats*(1-1e-20)+1e-20 collapses to this in fp32
    float nl = -flog_acc(u);     // -log(u) > 0
    return -flog_acc(nl);        // -log(-log(u))
}

__global__ __launch_bounds__(256)
void tdgs_pool_kernel(const float* __restrict__ x,
                      const float* __restrict__ temp,
                      float* __restrict__ out) {
    unsigned o = blockIdx.x * 256u + threadIdx.x;   // output index (b,c,ho,wo)
    unsigned wo = o % 56u;
    unsigned t1 = o / 56u;
    unsigned ho = t1 % 56u;
    unsigned t2 = t1 / 56u;          // b*128 + c
    unsigned c  = t2 % 128u;

    // temperature: relu + 0.1
    float T  = temp[(c * 56u + ho) * 56u + wo];
    float tt = fmaxf(T, 0.0f) + 0.1f;

    // x patch (2x2, row-major within patch)
    unsigned xoff = (t2 * 112u + 2u * ho) * 112u + 2u * wo;
    float2 a0 = *reinterpret_cast<const float2*>(x + xoff);
    float2 a1 = *reinterpret_cast<const float2*>(x + xoff + 112u);

    // 4 independent hashes (ILP-4): per-element counters 4o+k
    unsigned base = o * 4u;
    uint32_t r0 = tf_xor_0_42(base + 0u);
    uint32_t r1 = tf_xor_0_42(base + 1u);
    uint32_t r2 = tf_xor_0_42(base + 2u);
    uint32_t r3 = tf_xor_0_42(base + 3u);

    // z_k = x_k / t + g_k ; argmax with first-index-wins ties (matches jnp.argmax)
    float zb = __fdiv_rn(a0.x, tt) + gumbel_from_bits(r0);
    float xb = a0.x;
    float z;
    z = __fdiv_rn(a0.y, tt) + gumbel_from_bits(r1); if (z > zb) { zb = z; xb = a0.y; }
    z = __fdiv_rn(a1.x, tt) + gumbel_from_bits(r2); if (z > zb) { zb = z; xb = a1.x; }
    z = __fdiv_rn(a1.y, tt) + gumbel_from_bits(r3); if (z > zb) { zb = z; xb = a1.y; }
    out[o] = xb;
}

extern "C" void kernel_launch(void* const* d_in, const int* in_sizes, int n_in,
                              void* d_out, int out_size) {
    const float* x    = (const float*)d_in[0];   // (32,128,112,112) fp32
    const float* temp = (const float*)d_in[1];   // (128,56,56) fp32
    float* out        = (float*)d_out;           // (32,128,56,56) fp32

    // outputs = 32*128*56*56 = 12,845,056 = 256 * 50176 exactly
    tdgs_pool_kernel<<<50176, 256>>>(x, temp, out);
}

// round 3
// speedup vs baseline: 1.2723x; 1.2723x over previous
#include <cuda_runtime.h>
#include <stdint.h>

// TDGSPooling2d: gumbel-softmax hard pooling over 2x2 patches.
// out[b,c,ho,wo] = x_patch[argmax_k(x_patch[k]/temp[c,ho,wo] + g_k)]
//
// Noise: JAX partitionable threefry:
//   bits[i] = o0 ^ o1, (o0,o1) = threefry2x32(key=(0,42), counter=(0, i))
// u = bitcast(bits>>9 | 0x3f800000) - 1; u = max(1e-20, u); g = -log(-log(u))
//
// R3: forward pass only needs the ARGMAX of x/t + g, not softmax. Gumbel is
// computed with MUFU.LG2 (+ log1p polynomial near u=1 where MUFU's absolute
// error would be amplified). Error budget ~1e-6 absolute per score -> a
// handful of argmax flips vs the reference's float arithmetic, well under
// the 1e-3 rel_err threshold. Alu pipe (threefry SHF/LOP3) is the floor.

// ---------- threefry2x32, key = (0, 42), counter (0, c1), return o0^o1 ----
// ks0 = 0, ks1 = 42, ks2 = 0x1BD11BDA ^ 0 ^ 42 = 0x1BD11BF0
__device__ __forceinline__ uint32_t tf_xor_0_42(uint32_t c1) {
    const uint32_t ks1 = 42u;
    const uint32_t ks2 = 0x1BD11BF0u;
    uint32_t x0 = 0u;            // c0 (=0) + ks0 (=0)
    uint32_t x1 = c1 + ks1;
#define TFR(r) { x0 += x1; x1 = __funnelshift_l(x1, x1, r); x1 ^= x0; }
    TFR(13) TFR(15) TFR(26) TFR(6)
    x0 += ks1; x1 += ks2 + 1u;
    TFR(17) TFR(29) TFR(16) TFR(24)
    x0 += ks2; x1 += 2u;                 // ks0 + 2
    TFR(13) TFR(15) TFR(26) TFR(6)
    /* x0 += ks0 (=0) */ x1 += ks1 + 3u;
    TFR(17) TFR(29) TFR(16) TFR(24)
    x0 += ks1; x1 += ks2 + 4u;
    TFR(13) TFR(15) TFR(26) TFR(6)
    x0 += ks2; x1 += 5u;                 // ks0 + 5
#undef TFR
    return x0 ^ x1;
}

// ---------- fast gumbel: -log(-log(u)) via MUFU.LG2 ----------
// First log: MUFU absolute error ~2^-21.4 is amplified to huge RELATIVE error
// in -log(u) as u -> 1 (nl -> 0), which then corrupts the second log by O(1).
// Fix: for s = u-1 in (-0.08, 0] use a relative-accurate log1p polynomial
// (truncation rel err ~4e-8 at |s|=0.08). Branch-free select.
// Second log: argument nl in [1.19e-7, 46.1]; MUFU is ulp-relative there and
// absolute-accurate near nl=1, so gumbel abs error stays ~<=1e-6 uniformly.
__device__ __forceinline__ float gumbel_fast(uint32_t bits) {
    float u = __uint_as_float((bits >> 9) | 0x3f800000u) - 1.0f;
    u = fmaxf(u, 1e-20f);
    const float LN2 = 0.69314718055994530942f;
    // MUFU path
    float nl_m = __log2f(u) * -LN2;
    // log1p polynomial path: nl = -ln(1+s) = -s*(1 - s/2 + s^2/3 - ... )
    float s = u - 1.0f;                       // exact (Sterbenz) for u in [0.5,1]
    float p = fmaf(s, -1.0f / 6.0f, 1.0f / 5.0f);
    p = fmaf(p, s, -0.25f);
    p = fmaf(p, s, 1.0f / 3.0f);
    p = fmaf(p, s, -0.5f);
    p = fmaf(p, s, 1.0f);
    float nl_p = -s * p;
    float nl = (s > -0.08f) ? nl_p : nl_m;
    // second log
    return __log2f(nl) * -LN2;
}

__global__ __launch_bounds__(256)
void tdgs_pool_kernel(const float* __restrict__ x,
                      const float* __restrict__ temp,
                      float* __restrict__ out) {
    unsigned o = blockIdx.x * 256u + threadIdx.x;   // output index (b,c,ho,wo)
    unsigned wo = o % 56u;
    unsigned t1 = o / 56u;
    unsigned ho = t1 % 56u;
    unsigned t2 = t1 / 56u;          // b*128 + c
    unsigned c  = t2 % 128u;

    // temperature: relu + 0.1; one correctly-rounded reciprocal replaces 4 divs
    float T  = temp[(c * 56u + ho) * 56u + wo];
    float tt = fmaxf(T, 0.0f) + 0.1f;
    float rt = __frcp_rn(tt);

    // x patch (2x2, row-major within patch)
    unsigned xoff = (t2 * 112u + 2u * ho) * 112u + 2u * wo;
    float2 a0 = *reinterpret_cast<const float2*>(x + xoff);
    float2 a1 = *reinterpret_cast<const float2*>(x + xoff + 112u);

    // 4 independent hashes (ILP-4): per-element counters 4o+k
    unsigned base = o * 4u;
    uint32_t r0 = tf_xor_0_42(base + 0u);
    uint32_t r1 = tf_xor_0_42(base + 1u);
    uint32_t r2 = tf_xor_0_42(base + 2u);
    uint32_t r3 = tf_xor_0_42(base + 3u);

    // z_k = x_k/t + g_k ; argmax with first-index-wins ties
    float zb = fmaf(a0.x, rt, gumbel_fast(r0));
    float xb = a0.x;
    float z;
    z = fmaf(a0.y, rt, gumbel_fast(r1)); if (z > zb) { zb = z; xb = a0.y; }
    z = fmaf(a1.x, rt, gumbel_fast(r2)); if (z > zb) { zb = z; xb = a1.x; }
    z = fmaf(a1.y, rt, gumbel_fast(r3)); if (z > zb) { zb = z; xb = a1.y; }
    out[o] = xb;
}

extern "C" void kernel_launch(void* const* d_in, const int* in_sizes, int n_in,
                              void* d_out, int out_size) {
    const float* x    = (const float*)d_in[0];   // (32,128,112,112) fp32
    const float* temp = (const float*)d_in[1];   // (128,56,56) fp32
    float* out        = (float*)d_out;           // (32,128,56,56) fp32

    // outputs = 32*128*56*56 = 12,845,056 = 256 * 50176 exactly
    tdgs_pool_kernel<<<50176, 256>>>(x, temp, out);
}

// round 4
// speedup vs baseline: 1.3784x; 1.0833x over previous
#include <cuda_runtime.h>
#include <stdint.h>

// TDGSPooling2d: gumbel-softmax hard pooling over 2x2 patches (forward = argmax).
// out[b,c,ho,wo] = x_patch[argmax_k(x_patch[k]/temp[c,ho,wo] + g_k)]
// Noise: JAX partitionable threefry: bits[i] = o0^o1,
//   (o0,o1) = threefry2x32(key=(0,42), counter=(0,i))
//
// R4: (1) every threefry add forced onto the FMA pipe as a true IMAD
// (mad.lo.u32 with runtime-opaque multiplier 'one' = gridDim.y), balancing
// the alu pipe (SHF/LOP3, irreducible) against the fma pipe. (2) one thread
// produces the (b, b+16) output pair, sharing temperature/index math.

#define HALF_CNT 25690112u   // noise & x element offset between b and b+16
#define OUT_HALF 6422528u    // output element offset between b and b+16

// add on the FMA pipe: a*one + b, one==1 but unprovable by ptxas
__device__ __forceinline__ uint32_t addf(uint32_t a, uint32_t b, uint32_t one) {
    uint32_t r;
    asm("mad.lo.u32 %0, %1, %2, %3;" : "=r"(r) : "r"(a), "r"(one), "r"(b));
    return r;
}

__device__ __forceinline__ uint32_t rotl(uint32_t v, int r) {
    return __funnelshift_l(v, v, r);
}

// ---------- threefry2x32, key=(0,42), counter (0,c1), return o0^o1 ----------
// ks0 = 0, ks1 = 42, ks2 = 0x1BD11BDA ^ 0 ^ 42 = 0x1BD11BF0
__device__ __forceinline__ uint32_t tf_xor_0_42(uint32_t c1, uint32_t one) {
    const uint32_t ks1 = 42u;
    const uint32_t ks2 = 0x1BD11BF0u;
    uint32_t x1 = addf(c1, ks1, one);
    uint32_t x0 = x1;                 // round 1 add with x0 = c0+ks0 = 0
    x1 = rotl(x1, 13) ^ x0;
#define R(r) { x0 = addf(x1, x0, one); x1 = rotl(x1, (r)) ^ x0; }
    R(15) R(26) R(6)
    x0 = addf(x0, ks1, one);      x1 = addf(x1, ks2 + 1u, one);
    R(17) R(29) R(16) R(24)
    x0 = addf(x0, ks2, one);      x1 = addf(x1, 2u, one);        // ks0+2
    R(13) R(15) R(26) R(6)
    /* x0 += ks0 (=0) */          x1 = addf(x1, ks1 + 3u, one);
    R(17) R(29) R(16) R(24)
    x0 = addf(x0, ks1, one);      x1 = addf(x1, ks2 + 4u, one);
    R(13) R(15) R(26) R(6)
    x0 = addf(x0, ks2, one);      x1 = addf(x1, 5u, one);        // ks0+5
#undef R
    return x0 ^ x1;
}

// ---------- fast gumbel: -log(-log(u)) via MUFU.LG2 + near-1 log1p poly ----
// (unchanged from R3 — verified zero argmax flips vs the reference)
__device__ __forceinline__ float gumbel_fast(uint32_t bits) {
    float u = __uint_as_float((bits >> 9) | 0x3f800000u) - 1.0f;
    u = fmaxf(u, 1e-20f);
    const float LN2 = 0.69314718055994530942f;
    float nl_m = __log2f(u) * -LN2;
    float s = u - 1.0f;                       // exact for u in [0.5,1]
    float p = fmaf(s, -1.0f / 6.0f, 1.0f / 5.0f);
    p = fmaf(p, s, -0.25f);
    p = fmaf(p, s, 1.0f / 3.0f);
    p = fmaf(p, s, -0.5f);
    p = fmaf(p, s, 1.0f);
    float nl_p = -s * p;
    float nl = (s > -0.08f) ? nl_p : nl_m;
    return __log2f(nl) * -LN2;
}

__device__ __forceinline__ float argmax_pick(float2 v0, float2 v1, float rt,
                                             uint32_t r0, uint32_t r1,
                                             uint32_t r2, uint32_t r3) {
    float zb = fmaf(v0.x, rt, gumbel_fast(r0));
    float xb = v0.x;
    float z;
    z = fmaf(v0.y, rt, gumbel_fast(r1)); if (z > zb) { zb = z; xb = v0.y; }
    z = fmaf(v1.x, rt, gumbel_fast(r2)); if (z > zb) { zb = z; xb = v1.x; }
    z = fmaf(v1.y, rt, gumbel_fast(r3)); if (z > zb) { zb = z; xb = v1.y; }
    return xb;
}

__global__ __launch_bounds__(256)
void tdgs_pool_kernel(const float* __restrict__ x,
                      const float* __restrict__ temp,
                      float* __restrict__ out) {
    uint32_t one = gridDim.y;                       // == 1, opaque to ptxas
    unsigned p = blockIdx.x * 256u + threadIdx.x;   // pair index, b in [0,16)
    unsigned wo = p % 56u;
    unsigned t1 = p / 56u;
    unsigned ho = t1 % 56u;
    unsigned t2 = t1 / 56u;          // b*128 + c, b < 16
    unsigned c  = t2 % 128u;

    // temperature: relu + 0.1 -> one reciprocal, shared by both outputs
    float T  = temp[(c * 56u + ho) * 56u + wo];
    float tt = fmaxf(T, 0.0f) + 0.1f;
    float rt = __frcp_rn(tt);

    // x patches (2x2, row-major within patch) for b and b+16
    unsigned xoff = (t2 * 112u + 2u * ho) * 112u + 2u * wo;
    float2 a0 = *reinterpret_cast<const float2*>(x + xoff);
    float2 a1 = *reinterpret_cast<const float2*>(x + xoff + 112u);
    float2 b0 = *reinterpret_cast<const float2*>(x + xoff + HALF_CNT);
    float2 b1 = *reinterpret_cast<const float2*>(x + xoff + HALF_CNT + 112u);

    // 8 independent hashes; counters 4p+k and 4p+k+HALF_CNT
    unsigned base = p * 4u;
    uint32_t r0a = tf_xor_0_42(base + 0u, one);
    uint32_t r1a = tf_xor_0_42(base + 1u, one);
    uint32_t r2a = tf_xor_0_42(base + 2u, one);
    uint32_t r3a = tf_xor_0_42(base + 3u, one);
    uint32_t r0b = tf_xor_0_42(base + HALF_CNT + 0u, one);
    uint32_t r1b = tf_xor_0_42(base + HALF_CNT + 1u, one);
    uint32_t r2b = tf_xor_0_42(base + HALF_CNT + 2u, one);
    uint32_t r3b = tf_xor_0_42(base + HALF_CNT + 3u, one);

    out[p]            = argmax_pick(a0, a1, rt, r0a, r1a, r2a, r3a);
    out[p + OUT_HALF] = argmax_pick(b0, b1, rt, r0b, r1b, r2b, r3b);
}

extern "C" void kernel_launch(void* const* d_in, const int* in_sizes, int n_in,
                              void* d_out, int out_size) {
    const float* x    = (const float*)d_in[0];   // (32,128,112,112) fp32
    const float* temp = (const float*)d_in[1];   // (128,56,56) fp32
    float* out        = (float*)d_out;           // (32,128,56,56) fp32

    // pairs = 16*128*56*56 = 6,422,528 = 256 * 25088 exactly
    tdgs_pool_kernel<<<dim3(25088, 1, 1), 256>>>(x, temp, out);
}